// round 7
// baseline (speedup 1.0000x reference)
#include <cuda_runtime.h>

typedef unsigned long long u64;
typedef unsigned int u32;

// ---- packed f32x2 helpers ----
__device__ __forceinline__ u64 pk2(float a, float b) {
    u64 r; asm("mov.b64 %0,{%1,%2};" : "=l"(r) : "f"(a), "f"(b)); return r;
}
__device__ __forceinline__ u64 bc2(float a) {
    u64 r; asm("mov.b64 %0,{%1,%1};" : "=l"(r) : "f"(a)); return r;
}
__device__ __forceinline__ void upk2(u64 v, float& a, float& b) {
    asm("mov.b64 {%0,%1},%2;" : "=f"(a), "=f"(b) : "l"(v));
}
__device__ __forceinline__ u64 f2fma(u64 a, u64 b, u64 c) {
    u64 d; asm("fma.rn.f32x2 %0,%1,%2,%3;" : "=l"(d) : "l"(a), "l"(b), "l"(c)); return d;
}
__device__ __forceinline__ u64 f2mul(u64 a, u64 b) {
    u64 d; asm("mul.rn.f32x2 %0,%1,%2;" : "=l"(d) : "l"(a), "l"(b)); return d;
}
__device__ __forceinline__ u64 f2add(u64 a, u64 b) {
    u64 d; asm("add.rn.f32x2 %0,%1,%2;" : "=l"(d) : "l"(a), "l"(b)); return d;
}
__device__ __forceinline__ u64 f2sub(u64 a, u64 b) {   // FADD2: 2 operands
    u64 d; asm("sub.rn.f32x2 %0,%1,%2;" : "=l"(d) : "l"(a), "l"(b)); return d;
}
__device__ __forceinline__ u64 f2neg(u64 a) {          // LOP3 on ALU pipe
    return a ^ 0x8000000080000000ULL;
}
__device__ __forceinline__ float frcp(float a) {
    float r; asm("rcp.approx.f32 %0, %1;" : "=f"(r) : "f"(a)); return r;
}

// Single kernel, single graph node. Weight-derived gate constants are
// warp-uniform: computed ONCE PER BLOCK by thread 0 (accurate sincosf) into
// shared memory; all threads read them via LDS. This keeps the per-thread
// MUFU budget to the unavoidable per-sample x sincos only.
//
// smem layout (u64 each):
//  [6q+0..5], q=0..3 : A2, nA2, B2, nB2, C2, D2 for U=RZ(rz)@RY(ry)
//                      (A=c*zc, B=c*zs, C=s*zc, D=s*zs)
//  [24+q] q=0..2     : tan(wRY_q/2)      (layer-2 RY fast-Givens)
//  [27+q] q=0..2     : -tan(wRY_q/2)
//  [30]              : (c0*c1*c2)^2      (layer-2 RY cos product, squared)
//  [31]              : cos(w3)           (RY3 quadratic fold)
//  [32]              : -2*sin(w3)
__global__ void __launch_bounds__(128)
qml_main(const float* __restrict__ x, const float* __restrict__ w,
         float* __restrict__ out, int npairs) {
    __shared__ __align__(16) u64 sm[33];

    if (threadIdx.x == 0) {
        // layer-1 gates
#pragma unroll
        for (int q = 0; q < 4; q++) {
            float ry = w[q * 2 + 0], rz = w[q * 2 + 1];
            float s, c, zs, zc;
            sincosf(0.5f * ry, &s, &c);
            sincosf(0.5f * rz, &zs, &zc);
            float A = c * zc, Bv = c * zs, C = s * zc, D = s * zs;
            sm[6 * q + 0] = bc2(A);
            sm[6 * q + 1] = bc2(-A);
            sm[6 * q + 2] = bc2(Bv);
            sm[6 * q + 3] = bc2(-Bv);
            sm[6 * q + 4] = bc2(C);
            sm[6 * q + 5] = bc2(D);
        }
        // layer-2 RY scalars
        float s0, c0, s1, c1, s2, c2, s3, c3;
        sincosf(0.5f * w[8],  &s0, &c0);
        sincosf(0.5f * w[10], &s1, &c1);
        sincosf(0.5f * w[12], &s2, &c2);
        sincosf(0.5f * w[14], &s3, &c3);
        float t0 = s0 / c0, t1 = s1 / c1, t2 = s2 / c2;
        sm[24] = bc2(t0);  sm[25] = bc2(t1);  sm[26] = bc2(t2);
        sm[27] = bc2(-t0); sm[28] = bc2(-t1); sm[29] = bc2(-t2);
        float cp = c0 * c1 * c2;
        sm[30] = bc2(cp * cp);
        sm[31] = bc2(c3 * c3 - s3 * s3);   // cos(w3)
        sm[32] = bc2(-4.0f * c3 * s3);     // -2 sin(w3)
    }
    __syncthreads();

    int idx = blockIdx.x * blockDim.x + threadIdx.x;
    if (idx >= npairs) return;

    const float4* xg = reinterpret_cast<const float4*>(x);
    float4* o4 = reinterpret_cast<float4*>(out);

    float4 xa = xg[2 * idx];
    float4 xb = xg[2 * idx + 1];

    // ---- per-sample half-angle sin/cos + tan (shared by both RX layers) ----
    float caA[4], saA[4], caB[4], saB[4];
    __sincosf(0.5f * xa.x, &saA[0], &caA[0]);
    __sincosf(0.5f * xa.y, &saA[1], &caA[1]);
    __sincosf(0.5f * xa.z, &saA[2], &caA[2]);
    __sincosf(0.5f * xa.w, &saA[3], &caA[3]);
    __sincosf(0.5f * xb.x, &saB[0], &caB[0]);
    __sincosf(0.5f * xb.y, &saB[1], &caB[1]);
    __sincosf(0.5f * xb.z, &saB[2], &caB[2]);
    __sincosf(0.5f * xb.w, &saB[3], &caB[3]);

    u64 tx[4], ntx[4];
    u64 gc;
    {
        u64 c0 = pk2(caA[0], caB[0]);
        u64 c1 = pk2(caA[1], caB[1]);
        u64 c2 = pk2(caA[2], caB[2]);
        u64 c3 = pk2(caA[3], caB[3]);
        gc = f2mul(f2mul(c0, c1), f2mul(c2, c3));
#pragma unroll
        for (int q = 0; q < 4; q++) {
            u64 s2 = pk2(saA[q], saB[q]);
            u64 r2 = pk2(frcp(caA[q]), frcp(caB[q]));
            tx[q]  = f2mul(s2, r2);
            ntx[q] = f2neg(tx[q]);     // ALU pipe
        }
    }

    // ---- layer-1 gate factors (tan form): v' = U @ (1, -i t)^T
    //   vr0 = A + t*D;  vi0 = -B + t*C;  vr1 = C + t*B;  vi1 = D - t*A
    u64 vr[4][2], vi[4][2];
#pragma unroll
    for (int q = 0; q < 4; q++) {
        u64 A2  = sm[6 * q + 0];
        u64 nA2 = sm[6 * q + 1];
        u64 B2  = sm[6 * q + 2];
        u64 nB2 = sm[6 * q + 3];
        u64 C2  = sm[6 * q + 4];
        u64 D2  = sm[6 * q + 5];
        vr[q][0] = f2fma(tx[q], D2, A2);
        vi[q][0] = f2fma(tx[q], C2, nB2);
        vr[q][1] = f2fma(tx[q], B2, C2);
        vi[q][1] = f2fma(tx[q], nA2, D2);
    }

    // ---- per-sample global scale + pre-scaled RY3 fold constants ----
    u64 g2t, A3g, B3g;
    {
        u64 gc2 = f2mul(gc, gc);
        g2t = f2mul(f2mul(gc2, gc2), sm[30]);
        A3g = f2mul(sm[31], g2t);
        B3g = f2mul(sm[32], g2t);
    }

    // ==== Layer-2 RX gates commuted backward through layer-1's CNOTs:
    //   RX3 stays; RX2->RXX(2,3); RX1->RXX(1,2); RX0->RXX(0,1). Tan form. ====

    // RX(x3)/c on qubit-3 factor
    u64 wr[2], wi2[2];
    wr[0]  = f2fma(tx[3],  vi[3][1], vr[3][0]);
    wi2[0] = f2fma(ntx[3], vr[3][1], vi[3][0]);
    wr[1]  = f2fma(tx[3],  vi[3][0], vr[3][1]);
    wi2[1] = f2fma(ntx[3], vr[3][0], vi[3][1]);

    // Psi23 = v2' (x) w, then RXX(x2)/c (mask 3)
    u64 Qr[4], Qi[4];
    {
        u64 Pr[4], Pi[4];
        u64 nv2i0 = f2neg(vi[2][0]), nv2i1 = f2neg(vi[2][1]);
#pragma unroll
        for (int a = 0; a < 2; a++) {
            u64 ar = vr[2][a], ai = vi[2][a], nai = (a == 0) ? nv2i0 : nv2i1;
#pragma unroll
            for (int b = 0; b < 2; b++) {
                int j = a * 2 + b;
                Pr[j] = f2fma(nai, wi2[b], f2mul(ar, wr[b]));
                Pi[j] = f2fma(ai,  wr[b],  f2mul(ar, wi2[b]));
            }
        }
#pragma unroll
        for (int k = 0; k < 4; k++) {
            Qr[k] = f2fma(tx[2],  Pi[k ^ 3], Pr[k]);
            Qi[k] = f2fma(ntx[2], Pr[k ^ 3], Pi[k]);
        }
    }

    // Phi123 = v1' (x) Q, then RXX(x1)/c (mask 6). Fused pairwise.
    u64 Fr[8], Fi[8];
    {
        u64 nv1i0 = f2neg(vi[1][0]), nv1i1 = f2neg(vi[1][1]);
#pragma unroll
        for (int j = 0; j < 4; j++) {
            int j2 = j ^ 6;
            int t1 = j & 3, t2 = j2 & 3;   // a1=0, a2=1
            u64 p1r = f2fma(nv1i0,    Qi[t1], f2mul(vr[1][0], Qr[t1]));
            u64 p1i = f2fma(vi[1][0], Qr[t1], f2mul(vr[1][0], Qi[t1]));
            u64 p2r = f2fma(nv1i1,    Qi[t2], f2mul(vr[1][1], Qr[t2]));
            u64 p2i = f2fma(vi[1][1], Qr[t2], f2mul(vr[1][1], Qi[t2]));
            Fr[j]  = f2fma(tx[1],  p2i, p1r);
            Fi[j]  = f2fma(ntx[1], p2r, p1i);
            Fr[j2] = f2fma(tx[1],  p1i, p2r);
            Fi[j2] = f2fma(ntx[1], p1r, p2i);
        }
    }

    // Full state = v0' (x) F, then RXX(x0)/c (mask 12). Fused pairwise.
    u64 re[16], im[16];
    {
        u64 nv0i0 = f2neg(vi[0][0]), nv0i1 = f2neg(vi[0][1]);
#pragma unroll
        for (int t = 0; t < 8; t++) {
            int k1 = t;
            int k2 = 8 + (t ^ 4);
            int t2 = t ^ 4;
            u64 p1r = f2fma(nv0i0,    Fi[t],  f2mul(vr[0][0], Fr[t]));
            u64 p1i = f2fma(vi[0][0], Fr[t],  f2mul(vr[0][0], Fi[t]));
            u64 p2r = f2fma(nv0i1,    Fi[t2], f2mul(vr[0][1], Fr[t2]));
            u64 p2i = f2fma(vi[0][1], Fr[t2], f2mul(vr[0][1], Fi[t2]));
            re[k1] = f2fma(tx[0],  p2i, p1r);
            im[k1] = f2fma(ntx[0], p2r, p1i);
            re[k2] = f2fma(tx[0],  p1i, p2r);
            im[k2] = f2fma(ntx[0], p1r, p2i);
        }
    }

    // ---- layer-1 CNOT chain: basis permutation (register renames) ----
#pragma unroll
    for (int c = 0; c < 3; c++) {
        int bcm = 8 >> c, btm = 8 >> (c + 1);
#pragma unroll
        for (int k = 0; k < 16; k++)
            if ((k & bcm) && !(k & btm)) {
                u64 tr = re[k]; re[k] = re[k | btm]; re[k | btm] = tr;
                u64 ti = im[k]; im[k] = im[k | btm]; im[k | btm] = ti;
            }
    }

    // ---- layer-2 RY qubits 0..2, fast-Givens: n0 = a0 - t a1; n1 = t a0 + a1 ----
#pragma unroll
    for (int q = 0; q < 3; q++) {
        int bq = 8 >> q;
        u64 tq = sm[24 + q], ntq = sm[27 + q];
#pragma unroll
        for (int k = 0; k < 16; k++)
            if (!(k & bq)) {
                int k1 = k | bq;
                u64 n0r = f2fma(ntq, re[k1], re[k]);
                u64 n0i = f2fma(ntq, im[k1], im[k]);
                u64 n1r = f2fma(tq, re[k], re[k1]);
                u64 n1i = f2fma(tq, im[k], im[k1]);
                re[k] = n0r; im[k] = n0i; re[k1] = n1r; im[k1] = n1i;
            }
    }

    // ---- quadratics with RY3 fold:
    //   s01 = |a0|^2+|a1|^2          (scale applied at the very end)
    //   d01 = g2t*[cos(w3)(|a0|^2-|a1|^2) - 2 sin(w3)(r0r1+i0i1)]
    u64 s01[8], d01[8];
#pragma unroll
    for (int j = 0; j < 8; j++) {
        int k0 = 2 * j, k1 = 2 * j + 1;
        u64 q0 = f2fma(im[k0], im[k0], f2mul(re[k0], re[k0]));
        u64 q1 = f2fma(im[k1], im[k1], f2mul(re[k1], re[k1]));
        u64 xx = f2fma(im[k0], im[k1], f2mul(re[k0], re[k1]));
        s01[j] = f2add(q0, q1);
        u64 z  = f2sub(q0, q1);
        d01[j] = f2fma(B3g, xx, f2mul(A3g, z));
    }

    // ---- layer-2 CNOTs folded into measurement parities (Walsh) ----
    u64 z3p = f2add(f2add(d01[0], d01[3]), f2add(d01[5], d01[6]));
    u64 z3m = f2add(f2add(d01[1], d01[2]), f2add(d01[4], d01[7]));
    u64 Z3 = f2sub(z3p, z3m);

    u64 sq[4], dq[4];
#pragma unroll
    for (int m = 0; m < 4; m++) {
        sq[m] = f2add(s01[2 * m], s01[2 * m + 1]);
        dq[m] = f2sub(s01[2 * m], s01[2 * m + 1]);
    }
    u64 Z2 = f2mul(g2t, f2sub(f2add(dq[0], dq[3]), f2add(dq[1], dq[2])));
    u64 Z1 = f2mul(g2t, f2sub(f2add(sq[0], sq[3]), f2add(sq[1], sq[2])));
    u64 Z0 = f2mul(g2t, f2sub(f2add(sq[0], sq[1]), f2add(sq[2], sq[3])));

    // ---- unpack lanes and store ----
    float z0a, z0b, z1a, z1b, z2a, z2b, z3a, z3b;
    upk2(Z0, z0a, z0b); upk2(Z1, z1a, z1b);
    upk2(Z2, z2a, z2b); upk2(Z3, z3a, z3b);
    o4[2 * idx]     = make_float4(z0a, z1a, z2a, z3a);
    o4[2 * idx + 1] = make_float4(z0b, z1b, z2b, z3b);
}

extern "C" void kernel_launch(void* const* d_in, const int* in_sizes, int n_in,
                              void* d_out, int out_size) {
    const float* x = (const float*)d_in[0];       // [B,4] float32
    const float* w = (const float*)d_in[1];       // [2,4,2] float32
    float* out = (float*)d_out;                   // [B,4] float32
    int B = in_sizes[0] / 4;
    int npairs = B >> 1;                          // B = 2^20, even

    int block = 128;
    int grid = (npairs + block - 1) / block;
    qml_main<<<grid, block>>>(x, w, out, npairs);
}

// round 8
// speedup vs baseline: 1.1794x; 1.1794x over previous
#include <cuda_runtime.h>

typedef unsigned long long u64;
typedef unsigned int u32;

// ---- packed f32x2 helpers ----
__device__ __forceinline__ u64 pk2(float a, float b) {
    u64 r; asm("mov.b64 %0,{%1,%2};" : "=l"(r) : "f"(a), "f"(b)); return r;
}
__device__ __forceinline__ u64 bc2(float a) {
    u64 r; asm("mov.b64 %0,{%1,%1};" : "=l"(r) : "f"(a)); return r;
}
__device__ __forceinline__ void upk2(u64 v, float& a, float& b) {
    asm("mov.b64 {%0,%1},%2;" : "=f"(a), "=f"(b) : "l"(v));
}
__device__ __forceinline__ u64 f2fma(u64 a, u64 b, u64 c) {
    u64 d; asm("fma.rn.f32x2 %0,%1,%2,%3;" : "=l"(d) : "l"(a), "l"(b), "l"(c)); return d;
}
__device__ __forceinline__ u64 f2mul(u64 a, u64 b) {
    u64 d; asm("mul.rn.f32x2 %0,%1,%2;" : "=l"(d) : "l"(a), "l"(b)); return d;
}
__device__ __forceinline__ u64 f2add(u64 a, u64 b) {
    u64 d; asm("add.rn.f32x2 %0,%1,%2;" : "=l"(d) : "l"(a), "l"(b)); return d;
}
__device__ __forceinline__ u64 f2sub(u64 a, u64 b) {   // FADD2: 2 operands
    u64 d; asm("sub.rn.f32x2 %0,%1,%2;" : "=l"(d) : "l"(a), "l"(b)); return d;
}
__device__ __forceinline__ u64 f2neg(u64 a) {          // LOP3 on ALU pipe
    return a ^ 0x8000000080000000ULL;
}
__device__ __forceinline__ float frcp(float a) {
    float r; asm("rcp.approx.f32 %0, %1;" : "=f"(r) : "f"(a)); return r;
}

// Single kernel, single graph node. Weight-derived gate constants are
// warp-uniform: computed ONCE PER BLOCK by thread 0 into shared memory.
// CRITICAL (R7 lesson): the leader must use fast __sincosf (MUFU inline),
// not library sincosf — the accurate call's Payne-Hanek slow path costs
// thousands of cycles while the whole block waits at the barrier.
//
// smem layout (u64 each):
//  [6q+0..5], q=0..3 : A2, nA2, B2, nB2, C2, D2 for U=RZ(rz)@RY(ry)
//                      (A=c*zc, B=c*zs, C=s*zc, D=s*zs)
//  [24+q] q=0..2     : tan(wRY_q/2)      (layer-2 RY fast-Givens)
//  [27+q] q=0..2     : -tan(wRY_q/2)
//  [30]              : (c0*c1*c2)^2      (layer-2 RY cos product, squared)
//  [31]              : cos(w3)           (RY3 quadratic fold)
//  [32]              : -2*sin(w3)
__global__ void __launch_bounds__(128)
qml_main(const float* __restrict__ x, const float* __restrict__ w,
         float* __restrict__ out, int npairs) {
    __shared__ __align__(16) u64 sm[33];

    if (threadIdx.x == 0) {
        // layer-1 gates (fast MUFU sincos: weights span [0,2pi], no range issues)
#pragma unroll
        for (int q = 0; q < 4; q++) {
            float ry = w[q * 2 + 0], rz = w[q * 2 + 1];
            float s, c, zs, zc;
            __sincosf(0.5f * ry, &s, &c);
            __sincosf(0.5f * rz, &zs, &zc);
            float A = c * zc, Bv = c * zs, C = s * zc, D = s * zs;
            sm[6 * q + 0] = bc2(A);
            sm[6 * q + 1] = bc2(-A);
            sm[6 * q + 2] = bc2(Bv);
            sm[6 * q + 3] = bc2(-Bv);
            sm[6 * q + 4] = bc2(C);
            sm[6 * q + 5] = bc2(D);
        }
        // layer-2 RY scalars
        float s0, c0, s1, c1, s2, c2, s3, c3;
        __sincosf(0.5f * w[8],  &s0, &c0);
        __sincosf(0.5f * w[10], &s1, &c1);
        __sincosf(0.5f * w[12], &s2, &c2);
        __sincosf(0.5f * w[14], &s3, &c3);
        float t0 = s0 * frcp(c0), t1 = s1 * frcp(c1), t2 = s2 * frcp(c2);
        sm[24] = bc2(t0);  sm[25] = bc2(t1);  sm[26] = bc2(t2);
        sm[27] = bc2(-t0); sm[28] = bc2(-t1); sm[29] = bc2(-t2);
        float cp = c0 * c1 * c2;
        sm[30] = bc2(cp * cp);
        sm[31] = bc2(c3 * c3 - s3 * s3);   // cos(w3)
        sm[32] = bc2(-4.0f * c3 * s3);     // -2 sin(w3)
    }
    __syncthreads();

    int idx = blockIdx.x * blockDim.x + threadIdx.x;
    if (idx >= npairs) return;

    const float4* xg = reinterpret_cast<const float4*>(x);
    float4* o4 = reinterpret_cast<float4*>(out);

    float4 xa = xg[2 * idx];
    float4 xb = xg[2 * idx + 1];

    // ---- per-sample half-angle sin/cos + tan (shared by both RX layers) ----
    float caA[4], saA[4], caB[4], saB[4];
    __sincosf(0.5f * xa.x, &saA[0], &caA[0]);
    __sincosf(0.5f * xa.y, &saA[1], &caA[1]);
    __sincosf(0.5f * xa.z, &saA[2], &caA[2]);
    __sincosf(0.5f * xa.w, &saA[3], &caA[3]);
    __sincosf(0.5f * xb.x, &saB[0], &caB[0]);
    __sincosf(0.5f * xb.y, &saB[1], &caB[1]);
    __sincosf(0.5f * xb.z, &saB[2], &caB[2]);
    __sincosf(0.5f * xb.w, &saB[3], &caB[3]);

    u64 tx[4], ntx[4];
    u64 gc;
    {
        u64 c0 = pk2(caA[0], caB[0]);
        u64 c1 = pk2(caA[1], caB[1]);
        u64 c2 = pk2(caA[2], caB[2]);
        u64 c3 = pk2(caA[3], caB[3]);
        gc = f2mul(f2mul(c0, c1), f2mul(c2, c3));
#pragma unroll
        for (int q = 0; q < 4; q++) {
            u64 s2 = pk2(saA[q], saB[q]);
            u64 r2 = pk2(frcp(caA[q]), frcp(caB[q]));
            tx[q]  = f2mul(s2, r2);
            ntx[q] = f2neg(tx[q]);     // ALU pipe
        }
    }

    // ---- layer-1 gate factors (tan form): v' = U @ (1, -i t)^T
    //   vr0 = A + t*D;  vi0 = -B + t*C;  vr1 = C + t*B;  vi1 = D - t*A
    u64 vr[4][2], vi[4][2];
#pragma unroll
    for (int q = 0; q < 4; q++) {
        u64 A2  = sm[6 * q + 0];
        u64 nA2 = sm[6 * q + 1];
        u64 B2  = sm[6 * q + 2];
        u64 nB2 = sm[6 * q + 3];
        u64 C2  = sm[6 * q + 4];
        u64 D2  = sm[6 * q + 5];
        vr[q][0] = f2fma(tx[q], D2, A2);
        vi[q][0] = f2fma(tx[q], C2, nB2);
        vr[q][1] = f2fma(tx[q], B2, C2);
        vi[q][1] = f2fma(tx[q], nA2, D2);
    }

    // ---- per-sample global scale + pre-scaled RY3 fold constants ----
    u64 g2t, A3g, B3g;
    {
        u64 gc2 = f2mul(gc, gc);
        g2t = f2mul(f2mul(gc2, gc2), sm[30]);
        A3g = f2mul(sm[31], g2t);
        B3g = f2mul(sm[32], g2t);
    }

    // ==== Layer-2 RX gates commuted backward through layer-1's CNOTs:
    //   RX3 stays; RX2->RXX(2,3); RX1->RXX(1,2); RX0->RXX(0,1). Tan form. ====

    // RX(x3)/c on qubit-3 factor
    u64 wr[2], wi2[2];
    wr[0]  = f2fma(tx[3],  vi[3][1], vr[3][0]);
    wi2[0] = f2fma(ntx[3], vr[3][1], vi[3][0]);
    wr[1]  = f2fma(tx[3],  vi[3][0], vr[3][1]);
    wi2[1] = f2fma(ntx[3], vr[3][0], vi[3][1]);

    // Psi23 = v2' (x) w, then RXX(x2)/c (mask 3)
    u64 Qr[4], Qi[4];
    {
        u64 Pr[4], Pi[4];
        u64 nv2i0 = f2neg(vi[2][0]), nv2i1 = f2neg(vi[2][1]);
#pragma unroll
        for (int a = 0; a < 2; a++) {
            u64 ar = vr[2][a], ai = vi[2][a], nai = (a == 0) ? nv2i0 : nv2i1;
#pragma unroll
            for (int b = 0; b < 2; b++) {
                int j = a * 2 + b;
                Pr[j] = f2fma(nai, wi2[b], f2mul(ar, wr[b]));
                Pi[j] = f2fma(ai,  wr[b],  f2mul(ar, wi2[b]));
            }
        }
#pragma unroll
        for (int k = 0; k < 4; k++) {
            Qr[k] = f2fma(tx[2],  Pi[k ^ 3], Pr[k]);
            Qi[k] = f2fma(ntx[2], Pr[k ^ 3], Pi[k]);
        }
    }

    // Phi123 = v1' (x) Q, then RXX(x1)/c (mask 6). Fused pairwise.
    u64 Fr[8], Fi[8];
    {
        u64 nv1i0 = f2neg(vi[1][0]), nv1i1 = f2neg(vi[1][1]);
#pragma unroll
        for (int j = 0; j < 4; j++) {
            int j2 = j ^ 6;
            int t1 = j & 3, t2 = j2 & 3;   // a1=0, a2=1
            u64 p1r = f2fma(nv1i0,    Qi[t1], f2mul(vr[1][0], Qr[t1]));
            u64 p1i = f2fma(vi[1][0], Qr[t1], f2mul(vr[1][0], Qi[t1]));
            u64 p2r = f2fma(nv1i1,    Qi[t2], f2mul(vr[1][1], Qr[t2]));
            u64 p2i = f2fma(vi[1][1], Qr[t2], f2mul(vr[1][1], Qi[t2]));
            Fr[j]  = f2fma(tx[1],  p2i, p1r);
            Fi[j]  = f2fma(ntx[1], p2r, p1i);
            Fr[j2] = f2fma(tx[1],  p1i, p2r);
            Fi[j2] = f2fma(ntx[1], p1r, p2i);
        }
    }

    // Full state = v0' (x) F, then RXX(x0)/c (mask 12). Fused pairwise.
    u64 re[16], im[16];
    {
        u64 nv0i0 = f2neg(vi[0][0]), nv0i1 = f2neg(vi[0][1]);
#pragma unroll
        for (int t = 0; t < 8; t++) {
            int k1 = t;
            int k2 = 8 + (t ^ 4);
            int t2 = t ^ 4;
            u64 p1r = f2fma(nv0i0,    Fi[t],  f2mul(vr[0][0], Fr[t]));
            u64 p1i = f2fma(vi[0][0], Fr[t],  f2mul(vr[0][0], Fi[t]));
            u64 p2r = f2fma(nv0i1,    Fi[t2], f2mul(vr[0][1], Fr[t2]));
            u64 p2i = f2fma(vi[0][1], Fr[t2], f2mul(vr[0][1], Fi[t2]));
            re[k1] = f2fma(tx[0],  p2i, p1r);
            im[k1] = f2fma(ntx[0], p2r, p1i);
            re[k2] = f2fma(tx[0],  p1i, p2r);
            im[k2] = f2fma(ntx[0], p1r, p2i);
        }
    }

    // ---- layer-1 CNOT chain: basis permutation (register renames) ----
#pragma unroll
    for (int c = 0; c < 3; c++) {
        int bcm = 8 >> c, btm = 8 >> (c + 1);
#pragma unroll
        for (int k = 0; k < 16; k++)
            if ((k & bcm) && !(k & btm)) {
                u64 tr = re[k]; re[k] = re[k | btm]; re[k | btm] = tr;
                u64 ti = im[k]; im[k] = im[k | btm]; im[k | btm] = ti;
            }
    }

    // ---- layer-2 RY qubits 0..2, fast-Givens: n0 = a0 - t a1; n1 = t a0 + a1 ----
#pragma unroll
    for (int q = 0; q < 3; q++) {
        int bq = 8 >> q;
        u64 tq = sm[24 + q], ntq = sm[27 + q];
#pragma unroll
        for (int k = 0; k < 16; k++)
            if (!(k & bq)) {
                int k1 = k | bq;
                u64 n0r = f2fma(ntq, re[k1], re[k]);
                u64 n0i = f2fma(ntq, im[k1], im[k]);
                u64 n1r = f2fma(tq, re[k], re[k1]);
                u64 n1i = f2fma(tq, im[k], im[k1]);
                re[k] = n0r; im[k] = n0i; re[k1] = n1r; im[k1] = n1i;
            }
    }

    // ---- quadratics with RY3 fold:
    //   s01 = |a0|^2+|a1|^2          (scale applied at the very end)
    //   d01 = g2t*[cos(w3)(|a0|^2-|a1|^2) - 2 sin(w3)(r0r1+i0i1)]
    u64 s01[8], d01[8];
#pragma unroll
    for (int j = 0; j < 8; j++) {
        int k0 = 2 * j, k1 = 2 * j + 1;
        u64 q0 = f2fma(im[k0], im[k0], f2mul(re[k0], re[k0]));
        u64 q1 = f2fma(im[k1], im[k1], f2mul(re[k1], re[k1]));
        u64 xx = f2fma(im[k0], im[k1], f2mul(re[k0], re[k1]));
        s01[j] = f2add(q0, q1);
        u64 z  = f2sub(q0, q1);
        d01[j] = f2fma(B3g, xx, f2mul(A3g, z));
    }

    // ---- layer-2 CNOTs folded into measurement parities (Walsh) ----
    u64 z3p = f2add(f2add(d01[0], d01[3]), f2add(d01[5], d01[6]));
    u64 z3m = f2add(f2add(d01[1], d01[2]), f2add(d01[4], d01[7]));
    u64 Z3 = f2sub(z3p, z3m);

    u64 sq[4], dq[4];
#pragma unroll
    for (int m = 0; m < 4; m++) {
        sq[m] = f2add(s01[2 * m], s01[2 * m + 1]);
        dq[m] = f2sub(s01[2 * m], s01[2 * m + 1]);
    }
    u64 Z2 = f2mul(g2t, f2sub(f2add(dq[0], dq[3]), f2add(dq[1], dq[2])));
    u64 Z1 = f2mul(g2t, f2sub(f2add(sq[0], sq[3]), f2add(sq[1], sq[2])));
    u64 Z0 = f2mul(g2t, f2sub(f2add(sq[0], sq[1]), f2add(sq[2], sq[3])));

    // ---- unpack lanes and store ----
    float z0a, z0b, z1a, z1b, z2a, z2b, z3a, z3b;
    upk2(Z0, z0a, z0b); upk2(Z1, z1a, z1b);
    upk2(Z2, z2a, z2b); upk2(Z3, z3a, z3b);
    o4[2 * idx]     = make_float4(z0a, z1a, z2a, z3a);
    o4[2 * idx + 1] = make_float4(z0b, z1b, z2b, z3b);
}

extern "C" void kernel_launch(void* const* d_in, const int* in_sizes, int n_in,
                              void* d_out, int out_size) {
    const float* x = (const float*)d_in[0];       // [B,4] float32
    const float* w = (const float*)d_in[1];       // [2,4,2] float32
    float* out = (float*)d_out;                   // [B,4] float32
    int B = in_sizes[0] / 4;
    int npairs = B >> 1;                          // B = 2^20, even

    int block = 128;
    int grid = (npairs + block - 1) / block;
    qml_main<<<grid, block>>>(x, w, out, npairs);
}

// round 9
// speedup vs baseline: 1.1944x; 1.0127x over previous
#include <cuda_runtime.h>

typedef unsigned long long u64;
typedef unsigned int u32;

// ---- packed f32x2 helpers ----
__device__ __forceinline__ u64 pk2(float a, float b) {
    u64 r; asm("mov.b64 %0,{%1,%2};" : "=l"(r) : "f"(a), "f"(b)); return r;
}
__device__ __forceinline__ u64 bc2(float a) {
    u64 r; asm("mov.b64 %0,{%1,%1};" : "=l"(r) : "f"(a)); return r;
}
__device__ __forceinline__ void upk2(u64 v, float& a, float& b) {
    asm("mov.b64 {%0,%1},%2;" : "=f"(a), "=f"(b) : "l"(v));
}
__device__ __forceinline__ u64 f2fma(u64 a, u64 b, u64 c) {
    u64 d; asm("fma.rn.f32x2 %0,%1,%2,%3;" : "=l"(d) : "l"(a), "l"(b), "l"(c)); return d;
}
__device__ __forceinline__ u64 f2mul(u64 a, u64 b) {
    u64 d; asm("mul.rn.f32x2 %0,%1,%2;" : "=l"(d) : "l"(a), "l"(b)); return d;
}
__device__ __forceinline__ u64 f2add(u64 a, u64 b) {
    u64 d; asm("add.rn.f32x2 %0,%1,%2;" : "=l"(d) : "l"(a), "l"(b)); return d;
}
__device__ __forceinline__ u64 f2sub(u64 a, u64 b) {   // FADD2: 2 operands
    u64 d; asm("sub.rn.f32x2 %0,%1,%2;" : "=l"(d) : "l"(a), "l"(b)); return d;
}
__device__ __forceinline__ u64 f2neg(u64 a) {          // LOP3 on ALU pipe
    return a ^ 0x8000000080000000ULL;
}
__device__ __forceinline__ float frcp(float a) {
    float r; asm("rcp.approx.f32 %0, %1;" : "=f"(r) : "f"(a)); return r;
}

// Single kernel, single graph node (R6 base — the best-total variant).
// R9 deltas: __launch_bounds__(128,6) to force 6 blocks/SM (occupancy was the
// binder at 27%/4.3 warps/SMSP), with manual live-range trimming so the 85-reg
// cap spills minimally: no ntx[] array (negate at use, ALU pipe), layer-2
// weight constants kept as scalar floats, g2t/A3g/B3g built only at the
// quadratics stage (gc alone stays live through the expansion).
__global__ void __launch_bounds__(128, 6)
qml_main(const float* __restrict__ x, const float* __restrict__ w,
         float* __restrict__ out, int npairs) {
    int idx = blockIdx.x * blockDim.x + threadIdx.x;
    if (idx >= npairs) return;

    const float4* xg = reinterpret_cast<const float4*>(x);
    float4* o4 = reinterpret_cast<float4*>(out);

    float4 xa = xg[2 * idx];
    float4 xb = xg[2 * idx + 1];

    // ---- weight loads (warp-uniform, L1 broadcast) ----
    const float4* wv = reinterpret_cast<const float4*>(w);
    float4 w0 = wv[0];  // layer0: q0(ry,rz), q1(ry,rz)
    float4 w1 = wv[1];  // layer0: q2(ry,rz), q3(ry,rz)
    float4 w2 = wv[2];  // layer1: q0(ry,rz), q1(ry,rz)
    float4 w3 = wv[3];  // layer1: q2(ry,rz), q3(ry,rz)

    // ---- per-sample half-angle sin/cos + tan (shared by both RX layers) ----
    float caA[4], saA[4], caB[4], saB[4];
    __sincosf(0.5f * xa.x, &saA[0], &caA[0]);
    __sincosf(0.5f * xa.y, &saA[1], &caA[1]);
    __sincosf(0.5f * xa.z, &saA[2], &caA[2]);
    __sincosf(0.5f * xa.w, &saA[3], &caA[3]);
    __sincosf(0.5f * xb.x, &saB[0], &caB[0]);
    __sincosf(0.5f * xb.y, &saB[1], &caB[1]);
    __sincosf(0.5f * xb.z, &saB[2], &caB[2]);
    __sincosf(0.5f * xb.w, &saB[3], &caB[3]);

    u64 tx[4];
    u64 gc;     // prod of cos(x_q/2) over 4 qubits — only u64 that must
                // survive until the quadratics stage
    {
        u64 c0 = pk2(caA[0], caB[0]);
        u64 c1 = pk2(caA[1], caB[1]);
        u64 c2 = pk2(caA[2], caB[2]);
        u64 c3 = pk2(caA[3], caB[3]);
        gc = f2mul(f2mul(c0, c1), f2mul(c2, c3));
#pragma unroll
        for (int q = 0; q < 4; q++) {
            u64 s2 = pk2(saA[q], saB[q]);
            u64 r2 = pk2(frcp(caA[q]), frcp(caB[q]));
            tx[q] = f2mul(s2, r2);
        }
    }

    // ---- layer-1 gate factors, weight sincos fused & consumed immediately.
    //   U = RZ(rz)@RY(ry): A=c*zc, B=c*zs, C=s*zc, D=s*zs
    //   v' = U @ (1, -i t)^T:
    //   vr0 = A + t*D;  vi0 = -B + t*C;  vr1 = C + t*B;  vi1 = D - t*A
    u64 vr[4][2], vi[4][2];
    {
        float ryv[4] = { w0.x, w0.z, w1.x, w1.z };
        float rzv[4] = { w0.y, w0.w, w1.y, w1.w };
#pragma unroll
        for (int q = 0; q < 4; q++) {
            float s, c, zs, zc;
            __sincosf(0.5f * ryv[q], &s, &c);
            __sincosf(0.5f * rzv[q], &zs, &zc);
            float A = c * zc, Bv = c * zs, C = s * zc, D = s * zs;
            vr[q][0] = f2fma(tx[q], bc2(D),   bc2(A));
            vi[q][0] = f2fma(tx[q], bc2(C),   bc2(-Bv));
            vr[q][1] = f2fma(tx[q], bc2(Bv),  bc2(C));
            vi[q][1] = f2fma(tx[q], bc2(-A),  bc2(D));
        }
    }

    // ---- layer-2 weight scalars: keep as cheap scalar floats until needed ----
    u64 tw[3];                  // RY tan for qubits 0..2 (needed as u64 in RY loop)
    float cp2f, A3f, B3f;       // scale + RY3-fold constants (scalar until quadratics)
    {
        float s0, c0, s1, c1, s2, c2, s3, c3;
        __sincosf(0.5f * w2.x, &s0, &c0);
        __sincosf(0.5f * w2.z, &s1, &c1);
        __sincosf(0.5f * w3.x, &s2, &c2);
        __sincosf(0.5f * w3.z, &s3, &c3);
        tw[0] = bc2(s0 * frcp(c0));
        tw[1] = bc2(s1 * frcp(c1));
        tw[2] = bc2(s2 * frcp(c2));
        float cp = c0 * c1 * c2;
        cp2f = cp * cp;
        A3f = c3 * c3 - s3 * s3;    // cos(w3)
        B3f = -4.0f * c3 * s3;      // -2 sin(w3)
    }

    // ==== Layer-2 RX gates commuted backward through layer-1's CNOTs:
    //   RX3 stays; RX2->RXX(2,3); RX1->RXX(1,2); RX0->RXX(0,1). Tan form. ====

    // RX(x3)/c on qubit-3 factor
    u64 wr[2], wi2[2];
    {
        u64 ntx3 = f2neg(tx[3]);
        wr[0]  = f2fma(tx[3], vi[3][1], vr[3][0]);
        wi2[0] = f2fma(ntx3,  vr[3][1], vi[3][0]);
        wr[1]  = f2fma(tx[3], vi[3][0], vr[3][1]);
        wi2[1] = f2fma(ntx3,  vr[3][0], vi[3][1]);
    }

    // Psi23 = v2' (x) w, then RXX(x2)/c (mask 3)
    u64 Qr[4], Qi[4];
    {
        u64 Pr[4], Pi[4];
        u64 nv2i0 = f2neg(vi[2][0]), nv2i1 = f2neg(vi[2][1]);
#pragma unroll
        for (int a = 0; a < 2; a++) {
            u64 ar = vr[2][a], ai = vi[2][a], nai = (a == 0) ? nv2i0 : nv2i1;
#pragma unroll
            for (int b = 0; b < 2; b++) {
                int j = a * 2 + b;
                Pr[j] = f2fma(nai, wi2[b], f2mul(ar, wr[b]));
                Pi[j] = f2fma(ai,  wr[b],  f2mul(ar, wi2[b]));
            }
        }
        u64 ntx2 = f2neg(tx[2]);
#pragma unroll
        for (int k = 0; k < 4; k++) {
            Qr[k] = f2fma(tx[2], Pi[k ^ 3], Pr[k]);
            Qi[k] = f2fma(ntx2,  Pr[k ^ 3], Pi[k]);
        }
    }

    // Phi123 = v1' (x) Q, then RXX(x1)/c (mask 6). Fused pairwise.
    u64 Fr[8], Fi[8];
    {
        u64 nv1i0 = f2neg(vi[1][0]), nv1i1 = f2neg(vi[1][1]);
        u64 ntx1 = f2neg(tx[1]);
#pragma unroll
        for (int j = 0; j < 4; j++) {
            int j2 = j ^ 6;
            int t1 = j & 3, t2 = j2 & 3;   // a1=0, a2=1
            u64 p1r = f2fma(nv1i0,    Qi[t1], f2mul(vr[1][0], Qr[t1]));
            u64 p1i = f2fma(vi[1][0], Qr[t1], f2mul(vr[1][0], Qi[t1]));
            u64 p2r = f2fma(nv1i1,    Qi[t2], f2mul(vr[1][1], Qr[t2]));
            u64 p2i = f2fma(vi[1][1], Qr[t2], f2mul(vr[1][1], Qi[t2]));
            Fr[j]  = f2fma(tx[1], p2i, p1r);
            Fi[j]  = f2fma(ntx1,  p2r, p1i);
            Fr[j2] = f2fma(tx[1], p1i, p2r);
            Fi[j2] = f2fma(ntx1,  p1r, p2i);
        }
    }

    // Full state = v0' (x) F, then RXX(x0)/c (mask 12). Fused pairwise.
    u64 re[16], im[16];
    {
        u64 nv0i0 = f2neg(vi[0][0]), nv0i1 = f2neg(vi[0][1]);
        u64 ntx0 = f2neg(tx[0]);
#pragma unroll
        for (int t = 0; t < 8; t++) {
            int k1 = t;
            int k2 = 8 + (t ^ 4);
            int t2 = t ^ 4;
            u64 p1r = f2fma(nv0i0,    Fi[t],  f2mul(vr[0][0], Fr[t]));
            u64 p1i = f2fma(vi[0][0], Fr[t],  f2mul(vr[0][0], Fi[t]));
            u64 p2r = f2fma(nv0i1,    Fi[t2], f2mul(vr[0][1], Fr[t2]));
            u64 p2i = f2fma(vi[0][1], Fr[t2], f2mul(vr[0][1], Fi[t2]));
            re[k1] = f2fma(tx[0], p2i, p1r);
            im[k1] = f2fma(ntx0,  p2r, p1i);
            re[k2] = f2fma(tx[0], p1i, p2r);
            im[k2] = f2fma(ntx0,  p1r, p2i);
        }
    }

    // ---- layer-1 CNOT chain: basis permutation (register renames) ----
#pragma unroll
    for (int c = 0; c < 3; c++) {
        int bcm = 8 >> c, btm = 8 >> (c + 1);
#pragma unroll
        for (int k = 0; k < 16; k++)
            if ((k & bcm) && !(k & btm)) {
                u64 tr = re[k]; re[k] = re[k | btm]; re[k | btm] = tr;
                u64 ti = im[k]; im[k] = im[k | btm]; im[k | btm] = ti;
            }
    }

    // ---- layer-2 RY qubits 0..2, fast-Givens: n0 = a0 - t a1; n1 = t a0 + a1 ----
#pragma unroll
    for (int q = 0; q < 3; q++) {
        int bq = 8 >> q;
        u64 tq = tw[q];
        u64 ntq = f2neg(tq);
#pragma unroll
        for (int k = 0; k < 16; k++)
            if (!(k & bq)) {
                int k1 = k | bq;
                u64 n0r = f2fma(ntq, re[k1], re[k]);
                u64 n0i = f2fma(ntq, im[k1], im[k]);
                u64 n1r = f2fma(tq, re[k], re[k1]);
                u64 n1i = f2fma(tq, im[k], im[k1]);
                re[k] = n0r; im[k] = n0i; re[k1] = n1r; im[k1] = n1i;
            }
    }

    // ---- per-sample global scale, built only now (short live range):
    //   g2t = gc^4 * cp^2;  A3g = cos(w3)*g2t;  B3g = -2 sin(w3)*g2t
    u64 g2t, A3g, B3g;
    {
        u64 gc2 = f2mul(gc, gc);
        g2t = f2mul(f2mul(gc2, gc2), bc2(cp2f));
        A3g = f2mul(bc2(A3f), g2t);
        B3g = f2mul(bc2(B3f), g2t);
    }

    // ---- quadratics with RY3 fold:
    //   s01 = |a0|^2+|a1|^2          (scale applied at the very end)
    //   d01 = g2t*[cos(w3)(|a0|^2-|a1|^2) - 2 sin(w3)(r0r1+i0i1)]
    u64 s01[8], d01[8];
#pragma unroll
    for (int j = 0; j < 8; j++) {
        int k0 = 2 * j, k1 = 2 * j + 1;
        u64 q0 = f2fma(im[k0], im[k0], f2mul(re[k0], re[k0]));
        u64 q1 = f2fma(im[k1], im[k1], f2mul(re[k1], re[k1]));
        u64 xx = f2fma(im[k0], im[k1], f2mul(re[k0], re[k1]));
        s01[j] = f2add(q0, q1);
        u64 z  = f2sub(q0, q1);
        d01[j] = f2fma(B3g, xx, f2mul(A3g, z));
    }

    // ---- layer-2 CNOTs folded into measurement parities (Walsh) ----
    u64 z3p = f2add(f2add(d01[0], d01[3]), f2add(d01[5], d01[6]));
    u64 z3m = f2add(f2add(d01[1], d01[2]), f2add(d01[4], d01[7]));
    u64 Z3 = f2sub(z3p, z3m);

    u64 sq[4], dq[4];
#pragma unroll
    for (int m = 0; m < 4; m++) {
        sq[m] = f2add(s01[2 * m], s01[2 * m + 1]);
        dq[m] = f2sub(s01[2 * m], s01[2 * m + 1]);
    }
    u64 Z2 = f2mul(g2t, f2sub(f2add(dq[0], dq[3]), f2add(dq[1], dq[2])));
    u64 Z1 = f2mul(g2t, f2sub(f2add(sq[0], sq[3]), f2add(sq[1], sq[2])));
    u64 Z0 = f2mul(g2t, f2sub(f2add(sq[0], sq[1]), f2add(sq[2], sq[3])));

    // ---- unpack lanes and store ----
    float z0a, z0b, z1a, z1b, z2a, z2b, z3a, z3b;
    upk2(Z0, z0a, z0b); upk2(Z1, z1a, z1b);
    upk2(Z2, z2a, z2b); upk2(Z3, z3a, z3b);
    o4[2 * idx]     = make_float4(z0a, z1a, z2a, z3a);
    o4[2 * idx + 1] = make_float4(z0b, z1b, z2b, z3b);
}

extern "C" void kernel_launch(void* const* d_in, const int* in_sizes, int n_in,
                              void* d_out, int out_size) {
    const float* x = (const float*)d_in[0];       // [B,4] float32
    const float* w = (const float*)d_in[1];       // [2,4,2] float32
    float* out = (float*)d_out;                   // [B,4] float32
    int B = in_sizes[0] / 4;
    int npairs = B >> 1;                          // B = 2^20, even

    int block = 128;
    int grid = (npairs + block - 1) / block;
    qml_main<<<grid, block>>>(x, w, out, npairs);
}

// round 10
// speedup vs baseline: 1.2771x; 1.0693x over previous
#include <cuda_runtime.h>

typedef unsigned long long u64;
typedef unsigned int u32;

// ---- packed f32x2 helpers ----
__device__ __forceinline__ u64 pk2(float a, float b) {
    u64 r; asm("mov.b64 %0,{%1,%2};" : "=l"(r) : "f"(a), "f"(b)); return r;
}
__device__ __forceinline__ u64 bc2(float a) {
    u64 r; asm("mov.b64 %0,{%1,%1};" : "=l"(r) : "f"(a)); return r;
}
__device__ __forceinline__ void upk2(u64 v, float& a, float& b) {
    asm("mov.b64 {%0,%1},%2;" : "=f"(a), "=f"(b) : "l"(v));
}
__device__ __forceinline__ u64 f2fma(u64 a, u64 b, u64 c) {
    u64 d; asm("fma.rn.f32x2 %0,%1,%2,%3;" : "=l"(d) : "l"(a), "l"(b), "l"(c)); return d;
}
__device__ __forceinline__ u64 f2mul(u64 a, u64 b) {
    u64 d; asm("mul.rn.f32x2 %0,%1,%2;" : "=l"(d) : "l"(a), "l"(b)); return d;
}
__device__ __forceinline__ u64 f2add(u64 a, u64 b) {
    u64 d; asm("add.rn.f32x2 %0,%1,%2;" : "=l"(d) : "l"(a), "l"(b)); return d;
}
__device__ __forceinline__ u64 f2sub(u64 a, u64 b) {   // FADD2: 2 operands
    u64 d; asm("sub.rn.f32x2 %0,%1,%2;" : "=l"(d) : "l"(a), "l"(b)); return d;
}
__device__ __forceinline__ u64 f2neg(u64 a) {          // LOP3 on ALU pipe
    return a ^ 0x8000000080000000ULL;
}
__device__ __forceinline__ float frcp(float a) {
    float r; asm("rcp.approx.f32 %0, %1;" : "=f"(r) : "f"(a)); return r;
}

// Single kernel, single graph node (R6 base = best total so far).
// R10 delta: weight trig is warp-distributed — lane l computes ONE __sincosf
// of its assigned weight angle; all lanes gather the 24 scalars via shfl.
// Removes ~17 redundant MUFU ops/thread with no barrier (R7/R8 lesson) and
// no extra graph node (R5 lesson). No occupancy cap (R9 lesson).
__global__ void __launch_bounds__(128)
qml_main(const float* __restrict__ x, const float* __restrict__ w,
         float* __restrict__ out, int npairs) {
    const unsigned FULL = 0xffffffffu;
    int idx = blockIdx.x * blockDim.x + threadIdx.x;
    int lane = threadIdx.x & 31;
    // Clamp the load index so the whole warp stays active through the shfls;
    // only the final store is guarded. (Grid is exact for B=2^20 anyway.)
    int cidx = idx < npairs ? idx : npairs - 1;

    const float4* xg = reinterpret_cast<const float4*>(x);
    float4* o4 = reinterpret_cast<float4*>(out);

    float4 xa = xg[2 * cidx];
    float4 xb = xg[2 * cidx + 1];

    // ---- warp-distributed weight trig: lane l handles one angle ----
    //   lanes 0..7  : 0.5*w[l]        (layer-1 ry,rz for q0..q3)
    //   lanes 8..11 : 0.5*w[2l-8]     (layer-2 ry for q0..q3: w[8],w[10],w[12],w[14])
    //   lanes 12..31: dummy (w[0])
    float s_l, c_l, t_l;
    {
        int wi = lane < 8 ? lane : (lane < 12 ? 2 * lane - 8 : 0);
        __sincosf(0.5f * w[wi], &s_l, &c_l);
        t_l = s_l * frcp(c_l);   // used from lanes 8..10 only
    }

    // ---- per-sample half-angle sin/cos + tan (shared by both RX layers) ----
    float caA[4], saA[4], caB[4], saB[4];
    __sincosf(0.5f * xa.x, &saA[0], &caA[0]);
    __sincosf(0.5f * xa.y, &saA[1], &caA[1]);
    __sincosf(0.5f * xa.z, &saA[2], &caA[2]);
    __sincosf(0.5f * xa.w, &saA[3], &caA[3]);
    __sincosf(0.5f * xb.x, &saB[0], &caB[0]);
    __sincosf(0.5f * xb.y, &saB[1], &caB[1]);
    __sincosf(0.5f * xb.z, &saB[2], &caB[2]);
    __sincosf(0.5f * xb.w, &saB[3], &caB[3]);

    u64 tx[4];
    u64 gc;     // prod of cos(x_q/2) over 4 qubits
    {
        u64 c0 = pk2(caA[0], caB[0]);
        u64 c1 = pk2(caA[1], caB[1]);
        u64 c2 = pk2(caA[2], caB[2]);
        u64 c3 = pk2(caA[3], caB[3]);
        gc = f2mul(f2mul(c0, c1), f2mul(c2, c3));
#pragma unroll
        for (int q = 0; q < 4; q++) {
            u64 s2 = pk2(saA[q], saB[q]);
            u64 r2 = pk2(frcp(caA[q]), frcp(caB[q]));
            tx[q] = f2mul(s2, r2);
        }
    }

    // ---- layer-1 gate factors via shfl-gathered weight sincos.
    //   U = RZ(rz)@RY(ry): A=c*zc, B=c*zs, C=s*zc, D=s*zs
    //   v' = U @ (1, -i t)^T:
    //   vr0 = A + t*D;  vi0 = -B + t*C;  vr1 = C + t*B;  vi1 = D - t*A
    u64 vr[4][2], vi[4][2];
#pragma unroll
    for (int q = 0; q < 4; q++) {
        float sry = __shfl_sync(FULL, s_l, 2 * q);
        float cry = __shfl_sync(FULL, c_l, 2 * q);
        float srz = __shfl_sync(FULL, s_l, 2 * q + 1);
        float crz = __shfl_sync(FULL, c_l, 2 * q + 1);
        float A = cry * crz, Bv = cry * srz, C = sry * crz, D = sry * srz;
        vr[q][0] = f2fma(tx[q], bc2(D),  bc2(A));
        vi[q][0] = f2fma(tx[q], bc2(C),  bc2(-Bv));
        vr[q][1] = f2fma(tx[q], bc2(Bv), bc2(C));
        vi[q][1] = f2fma(tx[q], bc2(-A), bc2(D));
    }

    // ---- layer-2 weight scalars via shfl ----
    u64 tw[3];
    float cp2f, A3f, B3f;
    {
        tw[0] = bc2(__shfl_sync(FULL, t_l, 8));
        tw[1] = bc2(__shfl_sync(FULL, t_l, 9));
        tw[2] = bc2(__shfl_sync(FULL, t_l, 10));
        float c8  = __shfl_sync(FULL, c_l, 8);
        float c9  = __shfl_sync(FULL, c_l, 9);
        float c10 = __shfl_sync(FULL, c_l, 10);
        float cp = c8 * c9 * c10;
        cp2f = cp * cp;
        float s11 = __shfl_sync(FULL, s_l, 11);
        float c11 = __shfl_sync(FULL, c_l, 11);
        A3f = c11 * c11 - s11 * s11;    // cos(w3)
        B3f = -4.0f * c11 * s11;        // -2 sin(w3)
    }

    // ==== Layer-2 RX gates commuted backward through layer-1's CNOTs:
    //   RX3 stays; RX2->RXX(2,3); RX1->RXX(1,2); RX0->RXX(0,1). Tan form. ====

    // RX(x3)/c on qubit-3 factor
    u64 wr[2], wi2[2];
    {
        u64 ntx3 = f2neg(tx[3]);
        wr[0]  = f2fma(tx[3], vi[3][1], vr[3][0]);
        wi2[0] = f2fma(ntx3,  vr[3][1], vi[3][0]);
        wr[1]  = f2fma(tx[3], vi[3][0], vr[3][1]);
        wi2[1] = f2fma(ntx3,  vr[3][0], vi[3][1]);
    }

    // Psi23 = v2' (x) w, then RXX(x2)/c (mask 3)
    u64 Qr[4], Qi[4];
    {
        u64 Pr[4], Pi[4];
        u64 nv2i0 = f2neg(vi[2][0]), nv2i1 = f2neg(vi[2][1]);
#pragma unroll
        for (int a = 0; a < 2; a++) {
            u64 ar = vr[2][a], ai = vi[2][a], nai = (a == 0) ? nv2i0 : nv2i1;
#pragma unroll
            for (int b = 0; b < 2; b++) {
                int j = a * 2 + b;
                Pr[j] = f2fma(nai, wi2[b], f2mul(ar, wr[b]));
                Pi[j] = f2fma(ai,  wr[b],  f2mul(ar, wi2[b]));
            }
        }
        u64 ntx2 = f2neg(tx[2]);
#pragma unroll
        for (int k = 0; k < 4; k++) {
            Qr[k] = f2fma(tx[2], Pi[k ^ 3], Pr[k]);
            Qi[k] = f2fma(ntx2,  Pr[k ^ 3], Pi[k]);
        }
    }

    // Phi123 = v1' (x) Q, then RXX(x1)/c (mask 6). Fused pairwise.
    u64 Fr[8], Fi[8];
    {
        u64 nv1i0 = f2neg(vi[1][0]), nv1i1 = f2neg(vi[1][1]);
        u64 ntx1 = f2neg(tx[1]);
#pragma unroll
        for (int j = 0; j < 4; j++) {
            int j2 = j ^ 6;
            int t1 = j & 3, t2 = j2 & 3;   // a1=0, a2=1
            u64 p1r = f2fma(nv1i0,    Qi[t1], f2mul(vr[1][0], Qr[t1]));
            u64 p1i = f2fma(vi[1][0], Qr[t1], f2mul(vr[1][0], Qi[t1]));
            u64 p2r = f2fma(nv1i1,    Qi[t2], f2mul(vr[1][1], Qr[t2]));
            u64 p2i = f2fma(vi[1][1], Qr[t2], f2mul(vr[1][1], Qi[t2]));
            Fr[j]  = f2fma(tx[1], p2i, p1r);
            Fi[j]  = f2fma(ntx1,  p2r, p1i);
            Fr[j2] = f2fma(tx[1], p1i, p2r);
            Fi[j2] = f2fma(ntx1,  p1r, p2i);
        }
    }

    // Full state = v0' (x) F, then RXX(x0)/c (mask 12). Fused pairwise.
    u64 re[16], im[16];
    {
        u64 nv0i0 = f2neg(vi[0][0]), nv0i1 = f2neg(vi[0][1]);
        u64 ntx0 = f2neg(tx[0]);
#pragma unroll
        for (int t = 0; t < 8; t++) {
            int k1 = t;
            int k2 = 8 + (t ^ 4);
            int t2 = t ^ 4;
            u64 p1r = f2fma(nv0i0,    Fi[t],  f2mul(vr[0][0], Fr[t]));
            u64 p1i = f2fma(vi[0][0], Fr[t],  f2mul(vr[0][0], Fi[t]));
            u64 p2r = f2fma(nv0i1,    Fi[t2], f2mul(vr[0][1], Fr[t2]));
            u64 p2i = f2fma(vi[0][1], Fr[t2], f2mul(vr[0][1], Fi[t2]));
            re[k1] = f2fma(tx[0], p2i, p1r);
            im[k1] = f2fma(ntx0,  p2r, p1i);
            re[k2] = f2fma(tx[0], p1i, p2r);
            im[k2] = f2fma(ntx0,  p1r, p2i);
        }
    }

    // ---- layer-1 CNOT chain: basis permutation (register renames) ----
#pragma unroll
    for (int c = 0; c < 3; c++) {
        int bcm = 8 >> c, btm = 8 >> (c + 1);
#pragma unroll
        for (int k = 0; k < 16; k++)
            if ((k & bcm) && !(k & btm)) {
                u64 tr = re[k]; re[k] = re[k | btm]; re[k | btm] = tr;
                u64 ti = im[k]; im[k] = im[k | btm]; im[k | btm] = ti;
            }
    }

    // ---- layer-2 RY qubits 0..2, fast-Givens: n0 = a0 - t a1; n1 = t a0 + a1 ----
#pragma unroll
    for (int q = 0; q < 3; q++) {
        int bq = 8 >> q;
        u64 tq = tw[q];
        u64 ntq = f2neg(tq);
#pragma unroll
        for (int k = 0; k < 16; k++)
            if (!(k & bq)) {
                int k1 = k | bq;
                u64 n0r = f2fma(ntq, re[k1], re[k]);
                u64 n0i = f2fma(ntq, im[k1], im[k]);
                u64 n1r = f2fma(tq, re[k], re[k1]);
                u64 n1i = f2fma(tq, im[k], im[k1]);
                re[k] = n0r; im[k] = n0i; re[k1] = n1r; im[k1] = n1i;
            }
    }

    // ---- per-sample global scale (short live range):
    //   g2t = gc^4 * cp^2;  A3g = cos(w3)*g2t;  B3g = -2 sin(w3)*g2t
    u64 g2t, A3g, B3g;
    {
        u64 gc2 = f2mul(gc, gc);
        g2t = f2mul(f2mul(gc2, gc2), bc2(cp2f));
        A3g = f2mul(bc2(A3f), g2t);
        B3g = f2mul(bc2(B3f), g2t);
    }

    // ---- quadratics with RY3 fold:
    //   s01 = |a0|^2+|a1|^2          (scale applied at the very end)
    //   d01 = g2t*[cos(w3)(|a0|^2-|a1|^2) - 2 sin(w3)(r0r1+i0i1)]
    u64 s01[8], d01[8];
#pragma unroll
    for (int j = 0; j < 8; j++) {
        int k0 = 2 * j, k1 = 2 * j + 1;
        u64 q0 = f2fma(im[k0], im[k0], f2mul(re[k0], re[k0]));
        u64 q1 = f2fma(im[k1], im[k1], f2mul(re[k1], re[k1]));
        u64 xx = f2fma(im[k0], im[k1], f2mul(re[k0], re[k1]));
        s01[j] = f2add(q0, q1);
        u64 z  = f2sub(q0, q1);
        d01[j] = f2fma(B3g, xx, f2mul(A3g, z));
    }

    // ---- layer-2 CNOTs folded into measurement parities (Walsh) ----
    u64 z3p = f2add(f2add(d01[0], d01[3]), f2add(d01[5], d01[6]));
    u64 z3m = f2add(f2add(d01[1], d01[2]), f2add(d01[4], d01[7]));
    u64 Z3 = f2sub(z3p, z3m);

    u64 sq[4], dq[4];
#pragma unroll
    for (int m = 0; m < 4; m++) {
        sq[m] = f2add(s01[2 * m], s01[2 * m + 1]);
        dq[m] = f2sub(s01[2 * m], s01[2 * m + 1]);
    }
    u64 Z2 = f2mul(g2t, f2sub(f2add(dq[0], dq[3]), f2add(dq[1], dq[2])));
    u64 Z1 = f2mul(g2t, f2sub(f2add(sq[0], sq[3]), f2add(sq[1], sq[2])));
    u64 Z0 = f2mul(g2t, f2sub(f2add(sq[0], sq[1]), f2add(sq[2], sq[3])));

    // ---- unpack lanes and store (guarded; loads were clamp-indexed) ----
    if (idx < npairs) {
        float z0a, z0b, z1a, z1b, z2a, z2b, z3a, z3b;
        upk2(Z0, z0a, z0b); upk2(Z1, z1a, z1b);
        upk2(Z2, z2a, z2b); upk2(Z3, z3a, z3b);
        o4[2 * idx]     = make_float4(z0a, z1a, z2a, z3a);
        o4[2 * idx + 1] = make_float4(z0b, z1b, z2b, z3b);
    }
}

extern "C" void kernel_launch(void* const* d_in, const int* in_sizes, int n_in,
                              void* d_out, int out_size) {
    const float* x = (const float*)d_in[0];       // [B,4] float32
    const float* w = (const float*)d_in[1];       // [2,4,2] float32
    float* out = (float*)d_out;                   // [B,4] float32
    int B = in_sizes[0] / 4;
    int npairs = B >> 1;                          // B = 2^20, even

    int block = 128;
    int grid = (npairs + block - 1) / block;
    qml_main<<<grid, block>>>(x, w, out, npairs);
}

// round 11
// speedup vs baseline: 1.2947x; 1.0137x over previous
#include <cuda_runtime.h>

typedef unsigned long long u64;
typedef unsigned int u32;

// ---- packed f32x2 helpers ----
__device__ __forceinline__ u64 pk2(float a, float b) {
    u64 r; asm("mov.b64 %0,{%1,%2};" : "=l"(r) : "f"(a), "f"(b)); return r;
}
__device__ __forceinline__ u64 bc2(float a) {
    u64 r; asm("mov.b64 %0,{%1,%1};" : "=l"(r) : "f"(a)); return r;
}
__device__ __forceinline__ void upk2(u64 v, float& a, float& b) {
    asm("mov.b64 {%0,%1},%2;" : "=f"(a), "=f"(b) : "l"(v));
}
__device__ __forceinline__ u64 f2fma(u64 a, u64 b, u64 c) {
    u64 d; asm("fma.rn.f32x2 %0,%1,%2,%3;" : "=l"(d) : "l"(a), "l"(b), "l"(c)); return d;
}
__device__ __forceinline__ u64 f2mul(u64 a, u64 b) {
    u64 d; asm("mul.rn.f32x2 %0,%1,%2;" : "=l"(d) : "l"(a), "l"(b)); return d;
}
__device__ __forceinline__ u64 f2add(u64 a, u64 b) {
    u64 d; asm("add.rn.f32x2 %0,%1,%2;" : "=l"(d) : "l"(a), "l"(b)); return d;
}
__device__ __forceinline__ u64 f2sub(u64 a, u64 b) {   // FADD2: 2 operands
    u64 d; asm("sub.rn.f32x2 %0,%1,%2;" : "=l"(d) : "l"(a), "l"(b)); return d;
}
__device__ __forceinline__ u64 f2neg(u64 a) {          // LOP3 on ALU pipe
    return a ^ 0x8000000080000000ULL;
}
__device__ __forceinline__ float frcp(float a) {
    float r; asm("rcp.approx.f32 %0, %1;" : "=f"(r) : "f"(a)); return r;
}

// Single kernel, single graph node (R10 base).
// R11 delta: Z3's per-j d01 FMAs are distributed — Z3 = g2t*(A3*Σ±z_j + B3*Σ±xx_j)
// with signed accumulation chains, removing ~14 FMA-pipe ops from the
// measurement tail (the binding pipe).
__global__ void __launch_bounds__(128)
qml_main(const float* __restrict__ x, const float* __restrict__ w,
         float* __restrict__ out, int npairs) {
    const unsigned FULL = 0xffffffffu;
    int idx = blockIdx.x * blockDim.x + threadIdx.x;
    int lane = threadIdx.x & 31;
    int cidx = idx < npairs ? idx : npairs - 1;   // keep warp converged for shfl

    const float4* xg = reinterpret_cast<const float4*>(x);
    float4* o4 = reinterpret_cast<float4*>(out);

    float4 xa = xg[2 * cidx];
    float4 xb = xg[2 * cidx + 1];

    // ---- warp-distributed weight trig: lane l handles one angle ----
    //   lanes 0..7  : 0.5*w[l]     (layer-1 ry,rz for q0..q3)
    //   lanes 8..11 : 0.5*w[2l-8]  (layer-2 ry: w[8],w[10],w[12],w[14])
    float s_l, c_l, t_l;
    {
        int wi = lane < 8 ? lane : (lane < 12 ? 2 * lane - 8 : 0);
        __sincosf(0.5f * w[wi], &s_l, &c_l);
        t_l = s_l * frcp(c_l);
    }

    // ---- per-sample half-angle sin/cos + tan (shared by both RX layers) ----
    float caA[4], saA[4], caB[4], saB[4];
    __sincosf(0.5f * xa.x, &saA[0], &caA[0]);
    __sincosf(0.5f * xa.y, &saA[1], &caA[1]);
    __sincosf(0.5f * xa.z, &saA[2], &caA[2]);
    __sincosf(0.5f * xa.w, &saA[3], &caA[3]);
    __sincosf(0.5f * xb.x, &saB[0], &caB[0]);
    __sincosf(0.5f * xb.y, &saB[1], &caB[1]);
    __sincosf(0.5f * xb.z, &saB[2], &caB[2]);
    __sincosf(0.5f * xb.w, &saB[3], &caB[3]);

    u64 tx[4];
    u64 gc;     // prod of cos(x_q/2) over 4 qubits
    {
        u64 c0 = pk2(caA[0], caB[0]);
        u64 c1 = pk2(caA[1], caB[1]);
        u64 c2 = pk2(caA[2], caB[2]);
        u64 c3 = pk2(caA[3], caB[3]);
        gc = f2mul(f2mul(c0, c1), f2mul(c2, c3));
#pragma unroll
        for (int q = 0; q < 4; q++) {
            u64 s2 = pk2(saA[q], saB[q]);
            u64 r2 = pk2(frcp(caA[q]), frcp(caB[q]));
            tx[q] = f2mul(s2, r2);
        }
    }

    // ---- layer-1 gate factors via shfl-gathered weight sincos.
    //   U = RZ(rz)@RY(ry): A=c*zc, B=c*zs, C=s*zc, D=s*zs
    //   v' = U @ (1, -i t)^T:
    //   vr0 = A + t*D;  vi0 = -B + t*C;  vr1 = C + t*B;  vi1 = D - t*A
    u64 vr[4][2], vi[4][2];
#pragma unroll
    for (int q = 0; q < 4; q++) {
        float sry = __shfl_sync(FULL, s_l, 2 * q);
        float cry = __shfl_sync(FULL, c_l, 2 * q);
        float srz = __shfl_sync(FULL, s_l, 2 * q + 1);
        float crz = __shfl_sync(FULL, c_l, 2 * q + 1);
        float A = cry * crz, Bv = cry * srz, C = sry * crz, D = sry * srz;
        vr[q][0] = f2fma(tx[q], bc2(D),  bc2(A));
        vi[q][0] = f2fma(tx[q], bc2(C),  bc2(-Bv));
        vr[q][1] = f2fma(tx[q], bc2(Bv), bc2(C));
        vi[q][1] = f2fma(tx[q], bc2(-A), bc2(D));
    }

    // ---- layer-2 weight scalars via shfl ----
    u64 tw[3];
    float cp2f, A3f, B3f;
    {
        tw[0] = bc2(__shfl_sync(FULL, t_l, 8));
        tw[1] = bc2(__shfl_sync(FULL, t_l, 9));
        tw[2] = bc2(__shfl_sync(FULL, t_l, 10));
        float c8  = __shfl_sync(FULL, c_l, 8);
        float c9  = __shfl_sync(FULL, c_l, 9);
        float c10 = __shfl_sync(FULL, c_l, 10);
        float cp = c8 * c9 * c10;
        cp2f = cp * cp;
        float s11 = __shfl_sync(FULL, s_l, 11);
        float c11 = __shfl_sync(FULL, c_l, 11);
        A3f = c11 * c11 - s11 * s11;    // cos(w3)
        B3f = -4.0f * c11 * s11;        // -2 sin(w3)
    }

    // ==== Layer-2 RX gates commuted backward through layer-1's CNOTs:
    //   RX3 stays; RX2->RXX(2,3); RX1->RXX(1,2); RX0->RXX(0,1). Tan form. ====

    // RX(x3)/c on qubit-3 factor
    u64 wr[2], wi2[2];
    {
        u64 ntx3 = f2neg(tx[3]);
        wr[0]  = f2fma(tx[3], vi[3][1], vr[3][0]);
        wi2[0] = f2fma(ntx3,  vr[3][1], vi[3][0]);
        wr[1]  = f2fma(tx[3], vi[3][0], vr[3][1]);
        wi2[1] = f2fma(ntx3,  vr[3][0], vi[3][1]);
    }

    // Psi23 = v2' (x) w, then RXX(x2)/c (mask 3)
    u64 Qr[4], Qi[4];
    {
        u64 Pr[4], Pi[4];
        u64 nv2i0 = f2neg(vi[2][0]), nv2i1 = f2neg(vi[2][1]);
#pragma unroll
        for (int a = 0; a < 2; a++) {
            u64 ar = vr[2][a], ai = vi[2][a], nai = (a == 0) ? nv2i0 : nv2i1;
#pragma unroll
            for (int b = 0; b < 2; b++) {
                int j = a * 2 + b;
                Pr[j] = f2fma(nai, wi2[b], f2mul(ar, wr[b]));
                Pi[j] = f2fma(ai,  wr[b],  f2mul(ar, wi2[b]));
            }
        }
        u64 ntx2 = f2neg(tx[2]);
#pragma unroll
        for (int k = 0; k < 4; k++) {
            Qr[k] = f2fma(tx[2], Pi[k ^ 3], Pr[k]);
            Qi[k] = f2fma(ntx2,  Pr[k ^ 3], Pi[k]);
        }
    }

    // Phi123 = v1' (x) Q, then RXX(x1)/c (mask 6). Fused pairwise.
    u64 Fr[8], Fi[8];
    {
        u64 nv1i0 = f2neg(vi[1][0]), nv1i1 = f2neg(vi[1][1]);
        u64 ntx1 = f2neg(tx[1]);
#pragma unroll
        for (int j = 0; j < 4; j++) {
            int j2 = j ^ 6;
            int t1 = j & 3, t2 = j2 & 3;   // a1=0, a2=1
            u64 p1r = f2fma(nv1i0,    Qi[t1], f2mul(vr[1][0], Qr[t1]));
            u64 p1i = f2fma(vi[1][0], Qr[t1], f2mul(vr[1][0], Qi[t1]));
            u64 p2r = f2fma(nv1i1,    Qi[t2], f2mul(vr[1][1], Qr[t2]));
            u64 p2i = f2fma(vi[1][1], Qr[t2], f2mul(vr[1][1], Qi[t2]));
            Fr[j]  = f2fma(tx[1], p2i, p1r);
            Fi[j]  = f2fma(ntx1,  p2r, p1i);
            Fr[j2] = f2fma(tx[1], p1i, p2r);
            Fi[j2] = f2fma(ntx1,  p1r, p2i);
        }
    }

    // Full state = v0' (x) F, then RXX(x0)/c (mask 12). Fused pairwise.
    u64 re[16], im[16];
    {
        u64 nv0i0 = f2neg(vi[0][0]), nv0i1 = f2neg(vi[0][1]);
        u64 ntx0 = f2neg(tx[0]);
#pragma unroll
        for (int t = 0; t < 8; t++) {
            int k1 = t;
            int k2 = 8 + (t ^ 4);
            int t2 = t ^ 4;
            u64 p1r = f2fma(nv0i0,    Fi[t],  f2mul(vr[0][0], Fr[t]));
            u64 p1i = f2fma(vi[0][0], Fr[t],  f2mul(vr[0][0], Fi[t]));
            u64 p2r = f2fma(nv0i1,    Fi[t2], f2mul(vr[0][1], Fr[t2]));
            u64 p2i = f2fma(vi[0][1], Fr[t2], f2mul(vr[0][1], Fi[t2]));
            re[k1] = f2fma(tx[0], p2i, p1r);
            im[k1] = f2fma(ntx0,  p2r, p1i);
            re[k2] = f2fma(tx[0], p1i, p2r);
            im[k2] = f2fma(ntx0,  p1r, p2i);
        }
    }

    // ---- layer-1 CNOT chain: basis permutation (register renames) ----
#pragma unroll
    for (int c = 0; c < 3; c++) {
        int bcm = 8 >> c, btm = 8 >> (c + 1);
#pragma unroll
        for (int k = 0; k < 16; k++)
            if ((k & bcm) && !(k & btm)) {
                u64 tr = re[k]; re[k] = re[k | btm]; re[k | btm] = tr;
                u64 ti = im[k]; im[k] = im[k | btm]; im[k | btm] = ti;
            }
    }

    // ---- layer-2 RY qubits 0..2, fast-Givens: n0 = a0 - t a1; n1 = t a0 + a1 ----
#pragma unroll
    for (int q = 0; q < 3; q++) {
        int bq = 8 >> q;
        u64 tq = tw[q];
        u64 ntq = f2neg(tq);
#pragma unroll
        for (int k = 0; k < 16; k++)
            if (!(k & bq)) {
                int k1 = k | bq;
                u64 n0r = f2fma(ntq, re[k1], re[k]);
                u64 n0i = f2fma(ntq, im[k1], im[k]);
                u64 n1r = f2fma(tq, re[k], re[k1]);
                u64 n1i = f2fma(tq, im[k], im[k1]);
                re[k] = n0r; im[k] = n0i; re[k1] = n1r; im[k1] = n1i;
            }
    }

    // ---- quadratics; Z3 path DISTRIBUTED (R11):
    //   Z3 = g2t * [ A3 * Σ_j ±(q_{2j}-q_{2j+1})  +  B3 * Σ_j ±(r0r1+i0i1)_j ]
    //   with + for parity-even j {0,3,5,6}, − for {1,2,4,7}.
    //   s01[j] = q_{2j}+q_{2j+1} feeds Z0..Z2 as before.
    u64 s01[8];
    u64 z[8];
    u64 xxp, xxm;
#pragma unroll
    for (int j = 0; j < 8; j++) {
        int k0 = 2 * j, k1 = 2 * j + 1;
        u64 q0 = f2fma(im[k0], im[k0], f2mul(re[k0], re[k0]));
        u64 q1 = f2fma(im[k1], im[k1], f2mul(re[k1], re[k1]));
        s01[j] = f2add(q0, q1);
        z[j]   = f2sub(q0, q1);
        // signed xx accumulation: 2 FMAs per j into the right chain
        bool plus = (j == 0) | (j == 3) | (j == 5) | (j == 6);
        if (j == 0) {
            xxp = f2fma(im[k0], im[k1], f2mul(re[k0], re[k1]));
        } else if (j == 1) {
            xxm = f2fma(im[k0], im[k1], f2mul(re[k0], re[k1]));
        } else if (plus) {
            xxp = f2fma(re[k0], re[k1], xxp);
            xxp = f2fma(im[k0], im[k1], xxp);
        } else {
            xxm = f2fma(re[k0], re[k1], xxm);
            xxm = f2fma(im[k0], im[k1], xxm);
        }
    }
    u64 zsum  = f2sub(f2add(f2add(z[0], z[3]), f2add(z[5], z[6])),
                      f2add(f2add(z[1], z[2]), f2add(z[4], z[7])));
    u64 xxsum = f2sub(xxp, xxm);

    // ---- per-sample global scale ----
    u64 g2t;
    {
        u64 gc2 = f2mul(gc, gc);
        g2t = f2mul(f2mul(gc2, gc2), bc2(cp2f));
    }
    u64 Z3 = f2mul(g2t, f2fma(bc2(B3f), xxsum, f2mul(bc2(A3f), zsum)));

    // ---- layer-2 CNOTs folded into measurement parities (Walsh) ----
    u64 sq[4], dq[4];
#pragma unroll
    for (int m = 0; m < 4; m++) {
        sq[m] = f2add(s01[2 * m], s01[2 * m + 1]);
        dq[m] = f2sub(s01[2 * m], s01[2 * m + 1]);
    }
    u64 Z2 = f2mul(g2t, f2sub(f2add(dq[0], dq[3]), f2add(dq[1], dq[2])));
    u64 Z1 = f2mul(g2t, f2sub(f2add(sq[0], sq[3]), f2add(sq[1], sq[2])));
    u64 Z0 = f2mul(g2t, f2sub(f2add(sq[0], sq[1]), f2add(sq[2], sq[3])));

    // ---- unpack lanes and store (guarded; loads were clamp-indexed) ----
    if (idx < npairs) {
        float z0a, z0b, z1a, z1b, z2a, z2b, z3a, z3b;
        upk2(Z0, z0a, z0b); upk2(Z1, z1a, z1b);
        upk2(Z2, z2a, z2b); upk2(Z3, z3a, z3b);
        o4[2 * idx]     = make_float4(z0a, z1a, z2a, z3a);
        o4[2 * idx + 1] = make_float4(z0b, z1b, z2b, z3b);
    }
}

extern "C" void kernel_launch(void* const* d_in, const int* in_sizes, int n_in,
                              void* d_out, int out_size) {
    const float* x = (const float*)d_in[0];       // [B,4] float32
    const float* w = (const float*)d_in[1];       // [2,4,2] float32
    float* out = (float*)d_out;                   // [B,4] float32
    int B = in_sizes[0] / 4;
    int npairs = B >> 1;                          // B = 2^20, even

    int block = 128;
    int grid = (npairs + block - 1) / block;
    qml_main<<<grid, block>>>(x, w, out, npairs);
}